// round 2
// baseline (speedup 1.0000x reference)
#include <cuda_runtime.h>
#include <cuda_bf16.h>

#define NN 100000
#define NE 1600000
#define HD 64

// ---------------- scratch (device globals; no allocation allowed) ----------
__device__ int   g_deg[NN];
__device__ float g_inv[NN];
__device__ int   g_off[NN + 1];
__device__ int   g_bsum[128];
__device__ int   g_cnt[NN];
__device__ int   g_csr_src[NE];
__device__ float g_p  [NN * HD];   // projected neighbor features (p1, then p2)
__device__ float g_h1 [NN * HD];   // h1, later reused for hp
__device__ float g_h2 [NN * HD];
__device__ float g_srct[NN * 128]; // per-node: [hp@We1_src | hp@Wl1_src]
__device__ float g_dstt[NN * 128]; // per-node: [hp@We1_dst | hp@Wl1_dst]

__device__ __forceinline__ float tanh_fast(float x) {
    float y;
    asm("tanh.approx.f32 %0, %1;" : "=f"(y) : "f"(x));
    return y;
}

// ---------------- init ------------------------------------------------------
__global__ void k_zero() {
    int i = blockIdx.x * blockDim.x + threadIdx.x;
    int stride = gridDim.x * blockDim.x;
    for (int j = i; j < NN; j += stride) { g_deg[j] = 0; g_cnt[j] = 0; }
    if (i < 128) g_bsum[i] = 0;
}

// ---------------- degree histogram -----------------------------------------
__global__ void k_deg(const int* __restrict__ dst) {
    int e = blockIdx.x * blockDim.x + threadIdx.x;
    if (e < NE) atomicAdd(&g_deg[dst[e]], 1);
}

// ---------------- exclusive scan (3 kernels) --------------------------------
__global__ void k_scan1() {
    __shared__ int sh[1024];
    int tid = threadIdx.x;
    int i = blockIdx.x * 1024 + tid;
    int v = (i < NN) ? g_deg[i] : 0;
    sh[tid] = v;
    __syncthreads();
    for (int o = 1; o < 1024; o <<= 1) {
        int t = (tid >= o) ? sh[tid - o] : 0;
        __syncthreads();
        sh[tid] += t;
        __syncthreads();
    }
    if (i < NN) g_off[i] = sh[tid] - v;      // exclusive within block
    if (tid == 1023) g_bsum[blockIdx.x] = sh[1023];
}

__global__ void k_scan2(int nb) {
    if (threadIdx.x == 0 && blockIdx.x == 0) {
        int run = 0;
        for (int i = 0; i < nb; i++) { int t = g_bsum[i]; g_bsum[i] = run; run += t; }
        g_off[NN] = run;
    }
}

__global__ void k_scan3() {
    int i = blockIdx.x * blockDim.x + threadIdx.x;
    if (i < NN) {
        g_off[i] += g_bsum[i >> 10];
        int d = g_deg[i];
        g_inv[i] = 1.0f / (float)(d > 0 ? d : 1);
    }
}

// ---------------- CSR scatter ------------------------------------------------
__global__ void k_scatter(const int* __restrict__ src, const int* __restrict__ dst) {
    int e = blockIdx.x * blockDim.x + threadIdx.x;
    if (e < NE) {
        int d = dst[e];
        int pos = atomicAdd(&g_cnt[d], 1);
        g_csr_src[g_off[d] + pos] = src[e];
    }
}

// ---------------- p1 = node_feat @ W1n  (4 x 64) ----------------------------
__global__ void k_proj1(const float* __restrict__ nf, const float* __restrict__ W) {
    __shared__ float sW[4 * HD];
    int tid = threadIdx.x;
    sW[tid] = W[tid];                       // blockDim == 256 == 4*64
    __syncthreads();
    int idx = blockIdx.x * 256 + tid;
    if (idx >= NN * HD) return;
    int n = idx >> 6, f = idx & 63;
    const float* r = &nf[n * 4];
    float v = r[0] * sW[f] + r[1] * sW[64 + f] + r[2] * sW[128 + f] + r[3] * sW[192 + f];
    g_p[idx] = v;
}

// ---------------- SAGE layer 1: h1 = relu(nf@W1s + csr_sum(p1)*inv + b1) ----
__global__ void k_sage1(const float* __restrict__ nf, const float* __restrict__ Ws,
                        const float* __restrict__ b) {
    __shared__ float sW[4 * HD];
    int tid = threadIdx.x;
    sW[tid] = Ws[tid];
    __syncthreads();
    int n = blockIdx.x * 8 + (tid >> 5);
    int l = tid & 31;
    if (n >= NN) return;
    int beg = g_off[n], end = g_off[n + 1];
    float2 acc = make_float2(0.f, 0.f);
    int j = beg;
    for (; j + 4 <= end; j += 4) {          // MLP=4 to hide L2 latency
        int s0 = g_csr_src[j], s1 = g_csr_src[j + 1];
        int s2 = g_csr_src[j + 2], s3 = g_csr_src[j + 3];
        float2 q0 = *(const float2*)&g_p[s0 * HD + 2 * l];
        float2 q1 = *(const float2*)&g_p[s1 * HD + 2 * l];
        float2 q2 = *(const float2*)&g_p[s2 * HD + 2 * l];
        float2 q3 = *(const float2*)&g_p[s3 * HD + 2 * l];
        acc.x += (q0.x + q1.x) + (q2.x + q3.x);
        acc.y += (q0.y + q1.y) + (q2.y + q3.y);
    }
    for (; j < end; j++) {
        int s = g_csr_src[j];
        float2 q = *(const float2*)&g_p[s * HD + 2 * l];
        acc.x += q.x; acc.y += q.y;
    }
    float iv = g_inv[n];
    const float* r = &nf[n * 4];
    float n0 = r[0], n1 = r[1], n2 = r[2], n3 = r[3];
    float sx = n0 * sW[2 * l]     + n1 * sW[64 + 2 * l]     + n2 * sW[128 + 2 * l]     + n3 * sW[192 + 2 * l];
    float sy = n0 * sW[2 * l + 1] + n1 * sW[64 + 2 * l + 1] + n2 * sW[128 + 2 * l + 1] + n3 * sW[192 + 2 * l + 1];
    float2 o;
    o.x = fmaxf(sx + acc.x * iv + b[2 * l], 0.f);
    o.y = fmaxf(sy + acc.y * iv + b[2 * l + 1], 0.f);
    *(float2*)&g_h1[n * HD + 2 * l] = o;
}

// ---------------- generic 64x64 GEMV per node (warp/node) -------------------
__global__ void k_gemv64(const float* __restrict__ in, const float* __restrict__ W,
                         const float* __restrict__ bias, float* __restrict__ out, int doRelu) {
    __shared__ float sW[HD * HD];
    int tid = threadIdx.x;
    for (int i = tid; i < HD * HD; i += 256) sW[i] = W[i];
    __syncthreads();
    int n = blockIdx.x * 8 + (tid >> 5);
    int l = tid & 31;
    if (n >= NN) return;
    float r0 = in[n * HD + l], r1 = in[n * HD + 32 + l];
    float a0 = 0.f, a1 = 0.f;
#pragma unroll
    for (int k = 0; k < HD; k++) {
        float hk = __shfl_sync(0xffffffffu, (k < 32) ? r0 : r1, k & 31);
        float2 wv = *(const float2*)&sW[k * HD + 2 * l];
        a0 = fmaf(hk, wv.x, a0);
        a1 = fmaf(hk, wv.y, a1);
    }
    if (bias) { a0 += bias[2 * l]; a1 += bias[2 * l + 1]; }
    if (doRelu) { a0 = fmaxf(a0, 0.f); a1 = fmaxf(a1, 0.f); }
    *(float2*)&out[n * HD + 2 * l] = make_float2(a0, a1);
}

// ---------------- SAGE layer 2: h2 = relu(h1@W2s + csr_sum(p2)*inv + b2) ----
__global__ void k_sage2(const float* __restrict__ W2s, const float* __restrict__ b) {
    __shared__ float sW[HD * HD];
    int tid = threadIdx.x;
    for (int i = tid; i < HD * HD; i += 256) sW[i] = W2s[i];
    __syncthreads();
    int n = blockIdx.x * 8 + (tid >> 5);
    int l = tid & 31;
    if (n >= NN) return;
    float r0 = g_h1[n * HD + l], r1 = g_h1[n * HD + 32 + l];
    float a0 = 0.f, a1 = 0.f;
#pragma unroll
    for (int k = 0; k < HD; k++) {
        float hk = __shfl_sync(0xffffffffu, (k < 32) ? r0 : r1, k & 31);
        float2 wv = *(const float2*)&sW[k * HD + 2 * l];
        a0 = fmaf(hk, wv.x, a0);
        a1 = fmaf(hk, wv.y, a1);
    }
    int beg = g_off[n], end = g_off[n + 1];
    float2 acc = make_float2(0.f, 0.f);
    int j = beg;
    for (; j + 4 <= end; j += 4) {
        int s0 = g_csr_src[j], s1 = g_csr_src[j + 1];
        int s2 = g_csr_src[j + 2], s3 = g_csr_src[j + 3];
        float2 q0 = *(const float2*)&g_p[s0 * HD + 2 * l];
        float2 q1 = *(const float2*)&g_p[s1 * HD + 2 * l];
        float2 q2 = *(const float2*)&g_p[s2 * HD + 2 * l];
        float2 q3 = *(const float2*)&g_p[s3 * HD + 2 * l];
        acc.x += (q0.x + q1.x) + (q2.x + q3.x);
        acc.y += (q0.y + q1.y) + (q2.y + q3.y);
    }
    for (; j < end; j++) {
        int s = g_csr_src[j];
        float2 q = *(const float2*)&g_p[s * HD + 2 * l];
        acc.x += q.x; acc.y += q.y;
    }
    float iv = g_inv[n];
    float o0 = fmaxf(a0 + acc.x * iv + b[2 * l], 0.f);
    float o1 = fmaxf(a1 + acc.y * iv + b[2 * l + 1], 0.f);
    *(float2*)&g_h2[n * HD + 2 * l] = make_float2(o0, o1);
}

// -------- per-node tables: tab[n] = [hp@Wa | hp@Wb]  (Wa,Wb are 64x64) ------
__global__ void k_tab(const float* __restrict__ hp, const float* __restrict__ Wa,
                      const float* __restrict__ Wb, float* __restrict__ tab) {
    __shared__ float sWa[HD * HD];
    __shared__ float sWb[HD * HD];
    int tid = threadIdx.x;
    for (int i = tid; i < HD * HD; i += 256) { sWa[i] = Wa[i]; sWb[i] = Wb[i]; }
    __syncthreads();
    int n = blockIdx.x * 8 + (tid >> 5);
    int l = tid & 31;
    if (n >= NN) return;
    float r0 = hp[n * HD + l], r1 = hp[n * HD + 32 + l];
    float a0 = 0.f, a1 = 0.f, b0 = 0.f, b1 = 0.f;
#pragma unroll
    for (int k = 0; k < HD; k++) {
        float hk = __shfl_sync(0xffffffffu, (k < 32) ? r0 : r1, k & 31);
        float2 wa = *(const float2*)&sWa[k * HD + 2 * l];
        float2 wb = *(const float2*)&sWb[k * HD + 2 * l];
        a0 = fmaf(hk, wa.x, a0); a1 = fmaf(hk, wa.y, a1);
        b0 = fmaf(hk, wb.x, b0); b1 = fmaf(hk, wb.y, b1);
    }
    *(float2*)&tab[n * 128 + 2 * l]      = make_float2(a0, a1);
    *(float2*)&tab[n * 128 + 64 + 2 * l] = make_float2(b0, b1);
}

// ---------------- edge kernel: warp per edge --------------------------------
__global__ void k_edge(const int* __restrict__ src, const int* __restrict__ dst,
                       const float* __restrict__ ef,
                       const float* __restrict__ We1, const float* __restrict__ be1,
                       const float* __restrict__ We2, const float* __restrict__ be2,
                       const float* __restrict__ Wl1, const float* __restrict__ bl1,
                       const float* __restrict__ Wl2, const float* __restrict__ bl2,
                       float* __restrict__ out) {
    __shared__ float sWe[5 * HD], sWl[5 * HD];
    __shared__ float sWe2[HD], sWl2[HD], sbe1[HD], sbl1[HD];
    int tid = threadIdx.x;
    for (int i = tid; i < 5 * HD; i += 256) {
        sWe[i] = We1[128 * HD + i];         // edge_feat rows of We1 (rows 128..132)
        sWl[i] = Wl1[128 * HD + i];
    }
    if (tid < HD) {
        sWe2[tid] = We2[tid]; sWl2[tid] = Wl2[tid];
        sbe1[tid] = be1[tid]; sbl1[tid] = bl1[tid];
    }
    __syncthreads();
    int e = (blockIdx.x * 256 + tid) >> 5;
    int l = tid & 31;
    if (e >= NE) return;
    int s = __ldg(&src[e]);
    int d = __ldg(&dst[e]);
    const float2* ps = (const float2*)&g_srct[(size_t)s * 128];
    const float2* pd = (const float2*)&g_dstt[(size_t)d * 128];
    float2 a  = ps[l];       // hp[src]@We1_src part, feats 2l,2l+1
    float2 av = ps[32 + l];  // hp[src]@Wl1_src part
    float2 b  = pd[l];
    float2 bv = pd[32 + l];
    float efl = (l < 5) ? __ldg(&ef[(size_t)e * 5 + l]) : 0.f;

    float u0 = a.x + b.x + sbe1[2 * l];
    float u1 = a.y + b.y + sbe1[2 * l + 1];
    float v0 = av.x + bv.x;
    float v1 = av.y + bv.y;
#pragma unroll
    for (int k = 0; k < 5; k++) {
        float ek = __shfl_sync(0xffffffffu, efl, k);
        u0 = fmaf(ek, sWe[k * HD + 2 * l],     u0);
        u1 = fmaf(ek, sWe[k * HD + 2 * l + 1], u1);
        v0 = fmaf(ek, sWl[k * HD + 2 * l],     v0);
        v1 = fmaf(ek, sWl[k * HD + 2 * l + 1], v1);
    }
    float t0 = tanh_fast(u0);
    float t1 = tanh_fast(u1);
    float part = t0 * sWe2[2 * l] + t1 * sWe2[2 * l + 1];
#pragma unroll
    for (int o = 16; o > 0; o >>= 1) part += __shfl_xor_sync(0xffffffffu, part, o);
    float wgt = 1.f / (1.f + __expf(-(part + __ldg(be2))));
    float o0 = fmaxf(fmaf(wgt, v0, sbl1[2 * l]),     0.f);
    float o1 = fmaxf(fmaf(wgt, v1, sbl1[2 * l + 1]), 0.f);
    float p2 = o0 * sWl2[2 * l] + o1 * sWl2[2 * l + 1];
#pragma unroll
    for (int o = 16; o > 0; o >>= 1) p2 += __shfl_xor_sync(0xffffffffu, p2, o);
    if (l == 0) out[e] = p2 + __ldg(bl2);
}

// ---------------- launch -----------------------------------------------------
extern "C" void kernel_launch(void* const* d_in, const int* in_sizes, int n_in,
                              void* d_out, int out_size) {
    const float* node_feat = (const float*)d_in[0];
    const float* edge_feat = (const float*)d_in[1];
    const int*   src       = (const int*)d_in[2];
    const int*   dst       = (const int*)d_in[3];
    const float* W1s = (const float*)d_in[4];
    const float* W1n = (const float*)d_in[5];
    const float* b1  = (const float*)d_in[6];
    const float* W2s = (const float*)d_in[7];
    const float* W2n = (const float*)d_in[8];
    const float* b2  = (const float*)d_in[9];
    const float* Wnp = (const float*)d_in[10];
    const float* bnp = (const float*)d_in[11];
    const float* We1 = (const float*)d_in[12];
    const float* be1 = (const float*)d_in[13];
    const float* We2 = (const float*)d_in[14];
    const float* be2 = (const float*)d_in[15];
    const float* Wl1 = (const float*)d_in[16];
    const float* bl1 = (const float*)d_in[17];
    const float* Wl2 = (const float*)d_in[18];
    const float* bl2 = (const float*)d_in[19];
    float* out = (float*)d_out;

    float *pp, *ph1, *ph2, *pst, *pdt;
    cudaGetSymbolAddress((void**)&pp,  g_p);
    cudaGetSymbolAddress((void**)&ph1, g_h1);
    cudaGetSymbolAddress((void**)&ph2, g_h2);
    cudaGetSymbolAddress((void**)&pst, g_srct);
    cudaGetSymbolAddress((void**)&pdt, g_dstt);

    int nb = (NN + 1023) / 1024;
    int nblk = (NN + 7) / 8;

    k_zero<<<512, 256>>>();
    k_deg<<<(NE + 255) / 256, 256>>>(dst);
    k_scan1<<<nb, 1024>>>();
    k_scan2<<<1, 32>>>(nb);
    k_scan3<<<(NN + 255) / 256, 256>>>();
    k_scatter<<<(NE + 255) / 256, 256>>>(src, dst);

    // Layer 1
    k_proj1<<<(NN * HD + 255) / 256, 256>>>(node_feat, W1n);
    k_sage1<<<nblk, 256>>>(node_feat, W1s, b1);

    // Layer 2: p2 = h1@W2n into g_p, then combine
    k_gemv64<<<nblk, 256>>>(ph1, W2n, nullptr, pp, 0);
    k_sage2<<<nblk, 256>>>(W2s, b2);

    // hp = relu(h2@Wnp + bnp) into g_h1 (h1 no longer needed)
    k_gemv64<<<nblk, 256>>>(ph2, Wnp, bnp, ph1, 1);

    // per-node edge-MLP tables
    k_tab<<<nblk, 256>>>(ph1, We1,           Wl1,           pst); // src-role rows 0..63
    k_tab<<<nblk, 256>>>(ph1, We1 + 64 * HD, Wl1 + 64 * HD, pdt); // dst-role rows 64..127

    // fused edge stage
    k_edge<<<NE / 8, 256>>>(src, dst, edge_feat,
                            We1, be1, We2, be2, Wl1, bl1, Wl2, bl2, out);
}

// round 3
// speedup vs baseline: 1.0259x; 1.0259x over previous
#include <cuda_runtime.h>
#include <cuda_fp16.h>
#include <cuda_bf16.h>

#define NN 100000
#define NE 1600000
#define HD 64

// ---------------- scratch (device globals; no allocation allowed) ----------
__device__ int   g_deg[NN];
__device__ float g_inv[NN];
__device__ int   g_off[NN + 1];
__device__ int   g_bsum[128];
__device__ int   g_cnt[NN];
__device__ int   g_csr_src[NE];
__device__ float g_p  [NN * HD];   // projected neighbor features (p1, then p2)
__device__ float g_h1 [NN * HD];   // h1, later reused for hp
__device__ float g_h2 [NN * HD];
__device__ __half2 g_srct[NN * 64]; // per-node fp16: [hp@We1_src | hp@Wl1_src]
__device__ __half2 g_dstt[NN * 64]; // per-node fp16: [hp@We1_dst | hp@Wl1_dst]

__device__ __forceinline__ float tanh_fast(float x) {
    float y;
    asm("tanh.approx.f32 %0, %1;" : "=f"(y) : "f"(x));
    return y;
}

// ---------------- init ------------------------------------------------------
__global__ void k_zero() {
    int i = blockIdx.x * blockDim.x + threadIdx.x;
    int stride = gridDim.x * blockDim.x;
    for (int j = i; j < NN; j += stride) { g_deg[j] = 0; g_cnt[j] = 0; }
    if (i < 128) g_bsum[i] = 0;
}

// ---------------- degree histogram -----------------------------------------
__global__ void k_deg(const int* __restrict__ dst) {
    int e = blockIdx.x * blockDim.x + threadIdx.x;
    if (e < NE) atomicAdd(&g_deg[dst[e]], 1);
}

// ---------------- exclusive scan (3 kernels) --------------------------------
__global__ void k_scan1() {
    __shared__ int sh[1024];
    int tid = threadIdx.x;
    int i = blockIdx.x * 1024 + tid;
    int v = (i < NN) ? g_deg[i] : 0;
    sh[tid] = v;
    __syncthreads();
    for (int o = 1; o < 1024; o <<= 1) {
        int t = (tid >= o) ? sh[tid - o] : 0;
        __syncthreads();
        sh[tid] += t;
        __syncthreads();
    }
    if (i < NN) g_off[i] = sh[tid] - v;      // exclusive within block
    if (tid == 1023) g_bsum[blockIdx.x] = sh[1023];
}

// parallel scan over <=128 block sums (one block of 128 threads)
__global__ void k_scan2(int nb) {
    __shared__ int sh[128];
    int tid = threadIdx.x;
    int v = (tid < nb) ? g_bsum[tid] : 0;
    sh[tid] = v;
    __syncthreads();
    for (int o = 1; o < 128; o <<= 1) {
        int t = (tid >= o) ? sh[tid - o] : 0;
        __syncthreads();
        sh[tid] += t;
        __syncthreads();
    }
    g_bsum[tid] = sh[tid] - v;               // exclusive
    if (tid == 127) g_off[NN] = sh[127];
}

__global__ void k_scan3() {
    int i = blockIdx.x * blockDim.x + threadIdx.x;
    if (i < NN) {
        g_off[i] += g_bsum[i >> 10];
        int d = g_deg[i];
        g_inv[i] = 1.0f / (float)(d > 0 ? d : 1);
    }
}

// ---------------- CSR scatter ------------------------------------------------
__global__ void k_scatter(const int* __restrict__ src, const int* __restrict__ dst) {
    int e = blockIdx.x * blockDim.x + threadIdx.x;
    if (e < NE) {
        int d = dst[e];
        int pos = atomicAdd(&g_cnt[d], 1);
        g_csr_src[g_off[d] + pos] = src[e];
    }
}

// ---------------- p1 = node_feat @ W1n  (4 x 64) ----------------------------
__global__ void k_proj1(const float* __restrict__ nf, const float* __restrict__ W) {
    __shared__ float sW[4 * HD];
    int tid = threadIdx.x;
    sW[tid] = W[tid];                       // blockDim == 256 == 4*64
    __syncthreads();
    int idx = blockIdx.x * 256 + tid;
    if (idx >= NN * HD) return;
    int n = idx >> 6, f = idx & 63;
    const float* r = &nf[n * 4];
    float v = r[0] * sW[f] + r[1] * sW[64 + f] + r[2] * sW[128 + f] + r[3] * sW[192 + f];
    g_p[idx] = v;
}

// ---------------- SAGE layer 1: h1 = relu(nf@W1s + csr_sum(p1)*inv + b1) ----
__global__ void k_sage1(const float* __restrict__ nf, const float* __restrict__ Ws,
                        const float* __restrict__ b) {
    __shared__ float sW[4 * HD];
    int tid = threadIdx.x;
    sW[tid] = Ws[tid];
    __syncthreads();
    int n = blockIdx.x * 8 + (tid >> 5);
    int l = tid & 31;
    if (n >= NN) return;
    int beg = g_off[n], end = g_off[n + 1];
    float2 acc = make_float2(0.f, 0.f);
    int j = beg;
    for (; j + 4 <= end; j += 4) {          // MLP=4 to hide L2 latency
        int s0 = g_csr_src[j], s1 = g_csr_src[j + 1];
        int s2 = g_csr_src[j + 2], s3 = g_csr_src[j + 3];
        float2 q0 = *(const float2*)&g_p[s0 * HD + 2 * l];
        float2 q1 = *(const float2*)&g_p[s1 * HD + 2 * l];
        float2 q2 = *(const float2*)&g_p[s2 * HD + 2 * l];
        float2 q3 = *(const float2*)&g_p[s3 * HD + 2 * l];
        acc.x += (q0.x + q1.x) + (q2.x + q3.x);
        acc.y += (q0.y + q1.y) + (q2.y + q3.y);
    }
    for (; j < end; j++) {
        int s = g_csr_src[j];
        float2 q = *(const float2*)&g_p[s * HD + 2 * l];
        acc.x += q.x; acc.y += q.y;
    }
    float iv = g_inv[n];
    const float* r = &nf[n * 4];
    float n0 = r[0], n1 = r[1], n2 = r[2], n3 = r[3];
    float sx = n0 * sW[2 * l]     + n1 * sW[64 + 2 * l]     + n2 * sW[128 + 2 * l]     + n3 * sW[192 + 2 * l];
    float sy = n0 * sW[2 * l + 1] + n1 * sW[64 + 2 * l + 1] + n2 * sW[128 + 2 * l + 1] + n3 * sW[192 + 2 * l + 1];
    float2 o;
    o.x = fmaxf(sx + acc.x * iv + b[2 * l], 0.f);
    o.y = fmaxf(sy + acc.y * iv + b[2 * l + 1], 0.f);
    *(float2*)&g_h1[n * HD + 2 * l] = o;
}

// ---------------- generic 64x64 GEMV per node (warp/node) -------------------
__global__ void k_gemv64(const float* __restrict__ in, const float* __restrict__ W,
                         const float* __restrict__ bias, float* __restrict__ out, int doRelu) {
    __shared__ float sW[HD * HD];
    int tid = threadIdx.x;
    for (int i = tid; i < HD * HD; i += 256) sW[i] = W[i];
    __syncthreads();
    int n = blockIdx.x * 8 + (tid >> 5);
    int l = tid & 31;
    if (n >= NN) return;
    float r0 = in[n * HD + l], r1 = in[n * HD + 32 + l];
    float a0 = 0.f, a1 = 0.f;
#pragma unroll
    for (int k = 0; k < HD; k++) {
        float hk = __shfl_sync(0xffffffffu, (k < 32) ? r0 : r1, k & 31);
        float2 wv = *(const float2*)&sW[k * HD + 2 * l];
        a0 = fmaf(hk, wv.x, a0);
        a1 = fmaf(hk, wv.y, a1);
    }
    if (bias) { a0 += bias[2 * l]; a1 += bias[2 * l + 1]; }
    if (doRelu) { a0 = fmaxf(a0, 0.f); a1 = fmaxf(a1, 0.f); }
    *(float2*)&out[n * HD + 2 * l] = make_float2(a0, a1);
}

// ---------------- SAGE layer 2: h2 = relu(h1@W2s + csr_sum(p2)*inv + b2) ----
__global__ void k_sage2(const float* __restrict__ W2s, const float* __restrict__ b) {
    __shared__ float sW[HD * HD];
    int tid = threadIdx.x;
    for (int i = tid; i < HD * HD; i += 256) sW[i] = W2s[i];
    __syncthreads();
    int n = blockIdx.x * 8 + (tid >> 5);
    int l = tid & 31;
    if (n >= NN) return;
    float r0 = g_h1[n * HD + l], r1 = g_h1[n * HD + 32 + l];
    float a0 = 0.f, a1 = 0.f;
#pragma unroll
    for (int k = 0; k < HD; k++) {
        float hk = __shfl_sync(0xffffffffu, (k < 32) ? r0 : r1, k & 31);
        float2 wv = *(const float2*)&sW[k * HD + 2 * l];
        a0 = fmaf(hk, wv.x, a0);
        a1 = fmaf(hk, wv.y, a1);
    }
    int beg = g_off[n], end = g_off[n + 1];
    float2 acc = make_float2(0.f, 0.f);
    int j = beg;
    for (; j + 4 <= end; j += 4) {
        int s0 = g_csr_src[j], s1 = g_csr_src[j + 1];
        int s2 = g_csr_src[j + 2], s3 = g_csr_src[j + 3];
        float2 q0 = *(const float2*)&g_p[s0 * HD + 2 * l];
        float2 q1 = *(const float2*)&g_p[s1 * HD + 2 * l];
        float2 q2 = *(const float2*)&g_p[s2 * HD + 2 * l];
        float2 q3 = *(const float2*)&g_p[s3 * HD + 2 * l];
        acc.x += (q0.x + q1.x) + (q2.x + q3.x);
        acc.y += (q0.y + q1.y) + (q2.y + q3.y);
    }
    for (; j < end; j++) {
        int s = g_csr_src[j];
        float2 q = *(const float2*)&g_p[s * HD + 2 * l];
        acc.x += q.x; acc.y += q.y;
    }
    float iv = g_inv[n];
    float o0 = fmaxf(a0 + acc.x * iv + b[2 * l], 0.f);
    float o1 = fmaxf(a1 + acc.y * iv + b[2 * l + 1], 0.f);
    *(float2*)&g_h2[n * HD + 2 * l] = make_float2(o0, o1);
}

// -------- per-node tables (fp16): tab[n] = [hp@Wa | hp@Wb] ------------------
__global__ void k_tab(const float* __restrict__ hp, const float* __restrict__ Wa,
                      const float* __restrict__ Wb, __half2* __restrict__ tab) {
    __shared__ float sWa[HD * HD];
    __shared__ float sWb[HD * HD];
    int tid = threadIdx.x;
    for (int i = tid; i < HD * HD; i += 256) { sWa[i] = Wa[i]; sWb[i] = Wb[i]; }
    __syncthreads();
    int n = blockIdx.x * 8 + (tid >> 5);
    int l = tid & 31;
    if (n >= NN) return;
    float r0 = hp[n * HD + l], r1 = hp[n * HD + 32 + l];
    float a0 = 0.f, a1 = 0.f, b0 = 0.f, b1 = 0.f;
#pragma unroll
    for (int k = 0; k < HD; k++) {
        float hk = __shfl_sync(0xffffffffu, (k < 32) ? r0 : r1, k & 31);
        float2 wa = *(const float2*)&sWa[k * HD + 2 * l];
        float2 wb = *(const float2*)&sWb[k * HD + 2 * l];
        a0 = fmaf(hk, wa.x, a0); a1 = fmaf(hk, wa.y, a1);
        b0 = fmaf(hk, wb.x, b0); b1 = fmaf(hk, wb.y, b1);
    }
    tab[n * 64 + l]      = __floats2half2_rn(a0, a1);   // We-part, feats 2l,2l+1
    tab[n * 64 + 32 + l] = __floats2half2_rn(b0, b1);   // Wl-part
}

// ---------------- edge kernel: warp per edge, fp16 table gathers ------------
__global__ void k_edge(const int* __restrict__ src, const int* __restrict__ dst,
                       const float* __restrict__ ef,
                       const float* __restrict__ We1, const float* __restrict__ be1,
                       const float* __restrict__ We2, const float* __restrict__ be2,
                       const float* __restrict__ Wl1, const float* __restrict__ bl1,
                       const float* __restrict__ Wl2, const float* __restrict__ bl2,
                       float* __restrict__ out) {
    __shared__ float sWe[5 * HD], sWl[5 * HD];
    __shared__ float sWe2[HD], sWl2[HD], sbe1[HD], sbl1[HD];
    int tid = threadIdx.x;
    for (int i = tid; i < 5 * HD; i += 256) {
        sWe[i] = We1[128 * HD + i];         // edge_feat rows of We1 (rows 128..132)
        sWl[i] = Wl1[128 * HD + i];
    }
    if (tid < HD) {
        sWe2[tid] = We2[tid]; sWl2[tid] = Wl2[tid];
        sbe1[tid] = be1[tid]; sbl1[tid] = bl1[tid];
    }
    __syncthreads();
    int e = (blockIdx.x * 256 + tid) >> 5;
    int l = tid & 31;
    if (e >= NE) return;
    int s = __ldg(&src[e]);
    int d = __ldg(&dst[e]);
    const __half2* ps = &g_srct[(size_t)s * 64];
    const __half2* pd = &g_dstt[(size_t)d * 64];
    __half2 ha  = ps[l];        // We-part src
    __half2 hav = ps[32 + l];   // Wl-part src
    __half2 hb  = pd[l];
    __half2 hbv = pd[32 + l];
    float efl = (l < 5) ? __ldg(&ef[(size_t)e * 5 + l]) : 0.f;

    float2 a  = __half22float2(ha);
    float2 av = __half22float2(hav);
    float2 b  = __half22float2(hb);
    float2 bv = __half22float2(hbv);

    float u0 = a.x + b.x + sbe1[2 * l];
    float u1 = a.y + b.y + sbe1[2 * l + 1];
    float v0 = av.x + bv.x;
    float v1 = av.y + bv.y;
#pragma unroll
    for (int k = 0; k < 5; k++) {
        float ek = __shfl_sync(0xffffffffu, efl, k);
        u0 = fmaf(ek, sWe[k * HD + 2 * l],     u0);
        u1 = fmaf(ek, sWe[k * HD + 2 * l + 1], u1);
        v0 = fmaf(ek, sWl[k * HD + 2 * l],     v0);
        v1 = fmaf(ek, sWl[k * HD + 2 * l + 1], v1);
    }
    float t0 = tanh_fast(u0);
    float t1 = tanh_fast(u1);
    float part = t0 * sWe2[2 * l] + t1 * sWe2[2 * l + 1];
#pragma unroll
    for (int o = 16; o > 0; o >>= 1) part += __shfl_xor_sync(0xffffffffu, part, o);
    float wgt = 1.f / (1.f + __expf(-(part + __ldg(be2))));
    float o0 = fmaxf(fmaf(wgt, v0, sbl1[2 * l]),     0.f);
    float o1 = fmaxf(fmaf(wgt, v1, sbl1[2 * l + 1]), 0.f);
    float p2 = o0 * sWl2[2 * l] + o1 * sWl2[2 * l + 1];
#pragma unroll
    for (int o = 16; o > 0; o >>= 1) p2 += __shfl_xor_sync(0xffffffffu, p2, o);
    if (l == 0) out[e] = p2 + __ldg(bl2);
}

// ---------------- launch -----------------------------------------------------
extern "C" void kernel_launch(void* const* d_in, const int* in_sizes, int n_in,
                              void* d_out, int out_size) {
    const float* node_feat = (const float*)d_in[0];
    const float* edge_feat = (const float*)d_in[1];
    const int*   src       = (const int*)d_in[2];
    const int*   dst       = (const int*)d_in[3];
    const float* W1s = (const float*)d_in[4];
    const float* W1n = (const float*)d_in[5];
    const float* b1  = (const float*)d_in[6];
    const float* W2s = (const float*)d_in[7];
    const float* W2n = (const float*)d_in[8];
    const float* b2  = (const float*)d_in[9];
    const float* Wnp = (const float*)d_in[10];
    const float* bnp = (const float*)d_in[11];
    const float* We1 = (const float*)d_in[12];
    const float* be1 = (const float*)d_in[13];
    const float* We2 = (const float*)d_in[14];
    const float* be2 = (const float*)d_in[15];
    const float* Wl1 = (const float*)d_in[16];
    const float* bl1 = (const float*)d_in[17];
    const float* Wl2 = (const float*)d_in[18];
    const float* bl2 = (const float*)d_in[19];
    float* out = (float*)d_out;

    float *pp, *ph1, *ph2;
    __half2 *pst, *pdt;
    cudaGetSymbolAddress((void**)&pp,  g_p);
    cudaGetSymbolAddress((void**)&ph1, g_h1);
    cudaGetSymbolAddress((void**)&ph2, g_h2);
    cudaGetSymbolAddress((void**)&pst, g_srct);
    cudaGetSymbolAddress((void**)&pdt, g_dstt);

    int nb = (NN + 1023) / 1024;
    int nblk = (NN + 7) / 8;

    k_zero<<<512, 256>>>();
    k_deg<<<(NE + 255) / 256, 256>>>(dst);
    k_scan1<<<nb, 1024>>>();
    k_scan2<<<1, 128>>>(nb);
    k_scan3<<<(NN + 255) / 256, 256>>>();
    k_scatter<<<(NE + 255) / 256, 256>>>(src, dst);

    // Layer 1
    k_proj1<<<(NN * HD + 255) / 256, 256>>>(node_feat, W1n);
    k_sage1<<<nblk, 256>>>(node_feat, W1s, b1);

    // Layer 2: p2 = h1@W2n into g_p, then combine
    k_gemv64<<<nblk, 256>>>(ph1, W2n, nullptr, pp, 0);
    k_sage2<<<nblk, 256>>>(W2s, b2);

    // hp = relu(h2@Wnp + bnp) into g_h1 (h1 no longer needed)
    k_gemv64<<<nblk, 256>>>(ph2, Wnp, bnp, ph1, 1);

    // per-node edge-MLP tables (fp16)
    k_tab<<<nblk, 256>>>(ph1, We1,           Wl1,           pst); // src-role rows 0..63
    k_tab<<<nblk, 256>>>(ph1, We1 + 64 * HD, Wl1 + 64 * HD, pdt); // dst-role rows 64..127

    // fused edge stage
    k_edge<<<NE / 8, 256>>>(src, dst, edge_feat,
                            We1, be1, We2, be2, Wl1, bl1, Wl2, bl2, out);
}

// round 4
// speedup vs baseline: 1.0283x; 1.0023x over previous
#include <cuda_runtime.h>
#include <cuda_fp16.h>
#include <cuda_bf16.h>

#define NN 100000
#define NE 1600000
#define HD 64

// ---------------- scratch (device globals; no allocation allowed) ----------
__device__ int   g_deg[NN];
__device__ float g_inv[NN];
__device__ int   g_off[NN + 1];
__device__ int   g_bsum[128];
__device__ int   g_cnt[NN];
__device__ int   g_csr_src[NE];
__device__ float g_p  [NN * HD];   // projected neighbor features (p1, then p2)
__device__ float g_h1 [NN * HD];   // h1, later reused for hp
__device__ float g_h2 [NN * HD];
__device__ __half2 g_srct[NN * 64]; // per-node fp16: [hp@We1_src | hp@Wl1_src]
__device__ __half2 g_dstt[NN * 64]; // per-node fp16: [hp@We1_dst | hp@Wl1_dst]

__device__ __forceinline__ float tanh_fast(float x) {
    float y;
    asm("tanh.approx.f32 %0, %1;" : "=f"(y) : "f"(x));
    return y;
}

// ---------------- init ------------------------------------------------------
__global__ void k_zero() {
    int i = blockIdx.x * blockDim.x + threadIdx.x;
    int stride = gridDim.x * blockDim.x;
    for (int j = i; j < NN; j += stride) { g_deg[j] = 0; g_cnt[j] = 0; }
    if (i < 128) g_bsum[i] = 0;
}

// ---------------- degree histogram -----------------------------------------
__global__ void k_deg(const int* __restrict__ dst) {
    int e = blockIdx.x * blockDim.x + threadIdx.x;
    if (e < NE) atomicAdd(&g_deg[dst[e]], 1);
}

// ---------------- exclusive scan (3 kernels) --------------------------------
__global__ void k_scan1() {
    __shared__ int sh[1024];
    int tid = threadIdx.x;
    int i = blockIdx.x * 1024 + tid;
    int v = (i < NN) ? g_deg[i] : 0;
    sh[tid] = v;
    __syncthreads();
    for (int o = 1; o < 1024; o <<= 1) {
        int t = (tid >= o) ? sh[tid - o] : 0;
        __syncthreads();
        sh[tid] += t;
        __syncthreads();
    }
    if (i < NN) g_off[i] = sh[tid] - v;      // exclusive within block
    if (tid == 1023) g_bsum[blockIdx.x] = sh[1023];
}

// parallel scan over <=128 block sums (one block of 128 threads)
__global__ void k_scan2(int nb) {
    __shared__ int sh[128];
    int tid = threadIdx.x;
    int v = (tid < nb) ? g_bsum[tid] : 0;
    sh[tid] = v;
    __syncthreads();
    for (int o = 1; o < 128; o <<= 1) {
        int t = (tid >= o) ? sh[tid - o] : 0;
        __syncthreads();
        sh[tid] += t;
        __syncthreads();
    }
    g_bsum[tid] = sh[tid] - v;               // exclusive
    if (tid == 127) g_off[NN] = sh[127];
}

__global__ void k_scan3() {
    int i = blockIdx.x * blockDim.x + threadIdx.x;
    if (i < NN) {
        g_off[i] += g_bsum[i >> 10];
        int d = g_deg[i];
        g_inv[i] = 1.0f / (float)(d > 0 ? d : 1);
    }
}

// ---------------- CSR scatter ------------------------------------------------
__global__ void k_scatter(const int* __restrict__ src, const int* __restrict__ dst) {
    int e = blockIdx.x * blockDim.x + threadIdx.x;
    if (e < NE) {
        int d = dst[e];
        int pos = atomicAdd(&g_cnt[d], 1);
        g_csr_src[g_off[d] + pos] = src[e];
    }
}

// ---------------- p1 = node_feat @ W1n  (4 x 64) ----------------------------
__global__ void k_proj1(const float* __restrict__ nf, const float* __restrict__ W) {
    __shared__ float sW[4 * HD];
    int tid = threadIdx.x;
    sW[tid] = W[tid];                       // blockDim == 256 == 4*64
    __syncthreads();
    int idx = blockIdx.x * 256 + tid;
    if (idx >= NN * HD) return;
    int n = idx >> 6, f = idx & 63;
    const float* r = &nf[n * 4];
    float v = r[0] * sW[f] + r[1] * sW[64 + f] + r[2] * sW[128 + f] + r[3] * sW[192 + f];
    g_p[idx] = v;
}

// ---------------- SAGE layer 1: h1 = relu(nf@W1s + csr_sum(p1)*inv + b1) ----
__global__ void k_sage1(const float* __restrict__ nf, const float* __restrict__ Ws,
                        const float* __restrict__ b) {
    __shared__ float sW[4 * HD];
    int tid = threadIdx.x;
    sW[tid] = Ws[tid];
    __syncthreads();
    int n = blockIdx.x * 8 + (tid >> 5);
    int l = tid & 31;
    if (n >= NN) return;
    int beg = g_off[n], end = g_off[n + 1];
    float2 acc = make_float2(0.f, 0.f);
    int j = beg;
    for (; j + 4 <= end; j += 4) {          // MLP=4 to hide L2 latency
        int s0 = g_csr_src[j], s1 = g_csr_src[j + 1];
        int s2 = g_csr_src[j + 2], s3 = g_csr_src[j + 3];
        float2 q0 = *(const float2*)&g_p[s0 * HD + 2 * l];
        float2 q1 = *(const float2*)&g_p[s1 * HD + 2 * l];
        float2 q2 = *(const float2*)&g_p[s2 * HD + 2 * l];
        float2 q3 = *(const float2*)&g_p[s3 * HD + 2 * l];
        acc.x += (q0.x + q1.x) + (q2.x + q3.x);
        acc.y += (q0.y + q1.y) + (q2.y + q3.y);
    }
    for (; j < end; j++) {
        int s = g_csr_src[j];
        float2 q = *(const float2*)&g_p[s * HD + 2 * l];
        acc.x += q.x; acc.y += q.y;
    }
    float iv = g_inv[n];
    const float* r = &nf[n * 4];
    float n0 = r[0], n1 = r[1], n2 = r[2], n3 = r[3];
    float sx = n0 * sW[2 * l]     + n1 * sW[64 + 2 * l]     + n2 * sW[128 + 2 * l]     + n3 * sW[192 + 2 * l];
    float sy = n0 * sW[2 * l + 1] + n1 * sW[64 + 2 * l + 1] + n2 * sW[128 + 2 * l + 1] + n3 * sW[192 + 2 * l + 1];
    float2 o;
    o.x = fmaxf(sx + acc.x * iv + b[2 * l], 0.f);
    o.y = fmaxf(sy + acc.y * iv + b[2 * l + 1], 0.f);
    *(float2*)&g_h1[n * HD + 2 * l] = o;
}

// ---------------- generic 64x64 GEMV per node (warp/node) -------------------
__global__ void k_gemv64(const float* __restrict__ in, const float* __restrict__ W,
                         const float* __restrict__ bias, float* __restrict__ out, int doRelu) {
    __shared__ float sW[HD * HD];
    int tid = threadIdx.x;
    for (int i = tid; i < HD * HD; i += 256) sW[i] = W[i];
    __syncthreads();
    int n = blockIdx.x * 8 + (tid >> 5);
    int l = tid & 31;
    if (n >= NN) return;
    float r0 = in[n * HD + l], r1 = in[n * HD + 32 + l];
    float a0 = 0.f, a1 = 0.f;
#pragma unroll
    for (int k = 0; k < HD; k++) {
        float hk = __shfl_sync(0xffffffffu, (k < 32) ? r0 : r1, k & 31);
        float2 wv = *(const float2*)&sW[k * HD + 2 * l];
        a0 = fmaf(hk, wv.x, a0);
        a1 = fmaf(hk, wv.y, a1);
    }
    if (bias) { a0 += bias[2 * l]; a1 += bias[2 * l + 1]; }
    if (doRelu) { a0 = fmaxf(a0, 0.f); a1 = fmaxf(a1, 0.f); }
    *(float2*)&out[n * HD + 2 * l] = make_float2(a0, a1);
}

// ---------------- SAGE layer 2: h2 = relu(h1@W2s + csr_sum(p2)*inv + b2) ----
__global__ void k_sage2(const float* __restrict__ W2s, const float* __restrict__ b) {
    __shared__ float sW[HD * HD];
    int tid = threadIdx.x;
    for (int i = tid; i < HD * HD; i += 256) sW[i] = W2s[i];
    __syncthreads();
    int n = blockIdx.x * 8 + (tid >> 5);
    int l = tid & 31;
    if (n >= NN) return;
    float r0 = g_h1[n * HD + l], r1 = g_h1[n * HD + 32 + l];
    float a0 = 0.f, a1 = 0.f;
#pragma unroll
    for (int k = 0; k < HD; k++) {
        float hk = __shfl_sync(0xffffffffu, (k < 32) ? r0 : r1, k & 31);
        float2 wv = *(const float2*)&sW[k * HD + 2 * l];
        a0 = fmaf(hk, wv.x, a0);
        a1 = fmaf(hk, wv.y, a1);
    }
    int beg = g_off[n], end = g_off[n + 1];
    float2 acc = make_float2(0.f, 0.f);
    int j = beg;
    for (; j + 4 <= end; j += 4) {
        int s0 = g_csr_src[j], s1 = g_csr_src[j + 1];
        int s2 = g_csr_src[j + 2], s3 = g_csr_src[j + 3];
        float2 q0 = *(const float2*)&g_p[s0 * HD + 2 * l];
        float2 q1 = *(const float2*)&g_p[s1 * HD + 2 * l];
        float2 q2 = *(const float2*)&g_p[s2 * HD + 2 * l];
        float2 q3 = *(const float2*)&g_p[s3 * HD + 2 * l];
        acc.x += (q0.x + q1.x) + (q2.x + q3.x);
        acc.y += (q0.y + q1.y) + (q2.y + q3.y);
    }
    for (; j < end; j++) {
        int s = g_csr_src[j];
        float2 q = *(const float2*)&g_p[s * HD + 2 * l];
        acc.x += q.x; acc.y += q.y;
    }
    float iv = g_inv[n];
    float o0 = fmaxf(a0 + acc.x * iv + b[2 * l], 0.f);
    float o1 = fmaxf(a1 + acc.y * iv + b[2 * l + 1], 0.f);
    *(float2*)&g_h2[n * HD + 2 * l] = make_float2(o0, o1);
}

// -------- per-node tables (fp16): tab[n] = [hp@Wa | hp@Wb] ------------------
__global__ void k_tab(const float* __restrict__ hp, const float* __restrict__ Wa,
                      const float* __restrict__ Wb, __half2* __restrict__ tab) {
    __shared__ float sWa[HD * HD];
    __shared__ float sWb[HD * HD];
    int tid = threadIdx.x;
    for (int i = tid; i < HD * HD; i += 256) { sWa[i] = Wa[i]; sWb[i] = Wb[i]; }
    __syncthreads();
    int n = blockIdx.x * 8 + (tid >> 5);
    int l = tid & 31;
    if (n >= NN) return;
    float r0 = hp[n * HD + l], r1 = hp[n * HD + 32 + l];
    float a0 = 0.f, a1 = 0.f, b0 = 0.f, b1 = 0.f;
#pragma unroll
    for (int k = 0; k < HD; k++) {
        float hk = __shfl_sync(0xffffffffu, (k < 32) ? r0 : r1, k & 31);
        float2 wa = *(const float2*)&sWa[k * HD + 2 * l];
        float2 wb = *(const float2*)&sWb[k * HD + 2 * l];
        a0 = fmaf(hk, wa.x, a0); a1 = fmaf(hk, wa.y, a1);
        b0 = fmaf(hk, wb.x, b0); b1 = fmaf(hk, wb.y, b1);
    }
    tab[n * 64 + l]      = __floats2half2_rn(a0, a1);   // We-part, feats 2l,2l+1
    tab[n * 64 + 32 + l] = __floats2half2_rn(b0, b1);   // Wl-part
}

// ---------------- edge kernel: warp per edge, fp16 table gathers ------------
__global__ void k_edge(const int* __restrict__ src, const int* __restrict__ dst,
                       const float* __restrict__ ef,
                       const float* __restrict__ We1, const float* __restrict__ be1,
                       const float* __restrict__ We2, const float* __restrict__ be2,
                       const float* __restrict__ Wl1, const float* __restrict__ bl1,
                       const float* __restrict__ Wl2, const float* __restrict__ bl2,
                       float* __restrict__ out) {
    __shared__ float sWe[5 * HD], sWl[5 * HD];
    __shared__ float sWe2[HD], sWl2[HD], sbe1[HD], sbl1[HD];
    int tid = threadIdx.x;
    for (int i = tid; i < 5 * HD; i += 256) {
        sWe[i] = We1[128 * HD + i];         // edge_feat rows of We1 (rows 128..132)
        sWl[i] = Wl1[128 * HD + i];
    }
    if (tid < HD) {
        sWe2[tid] = We2[tid]; sWl2[tid] = Wl2[tid];
        sbe1[tid] = be1[tid]; sbl1[tid] = bl1[tid];
    }
    __syncthreads();
    int e = (blockIdx.x * 256 + tid) >> 5;
    int l = tid & 31;
    if (e >= NE) return;
    int s = __ldg(&src[e]);
    int d = __ldg(&dst[e]);
    const __half2* ps = &g_srct[(size_t)s * 64];
    const __half2* pd = &g_dstt[(size_t)d * 64];
    __half2 ha  = ps[l];        // We-part src
    __half2 hav = ps[32 + l];   // Wl-part src
    __half2 hb  = pd[l];
    __half2 hbv = pd[32 + l];
    float efl = (l < 5) ? __ldg(&ef[(size_t)e * 5 + l]) : 0.f;

    float2 a  = __half22float2(ha);
    float2 av = __half22float2(hav);
    float2 b  = __half22float2(hb);
    float2 bv = __half22float2(hbv);

    float u0 = a.x + b.x + sbe1[2 * l];
    float u1 = a.y + b.y + sbe1[2 * l + 1];
    float v0 = av.x + bv.x;
    float v1 = av.y + bv.y;
#pragma unroll
    for (int k = 0; k < 5; k++) {
        float ek = __shfl_sync(0xffffffffu, efl, k);
        u0 = fmaf(ek, sWe[k * HD + 2 * l],     u0);
        u1 = fmaf(ek, sWe[k * HD + 2 * l + 1], u1);
        v0 = fmaf(ek, sWl[k * HD + 2 * l],     v0);
        v1 = fmaf(ek, sWl[k * HD + 2 * l + 1], v1);
    }
    float t0 = tanh_fast(u0);
    float t1 = tanh_fast(u1);
    float part = t0 * sWe2[2 * l] + t1 * sWe2[2 * l + 1];
#pragma unroll
    for (int o = 16; o > 0; o >>= 1) part += __shfl_xor_sync(0xffffffffu, part, o);
    float wgt = 1.f / (1.f + __expf(-(part + __ldg(be2))));
    float o0 = fmaxf(fmaf(wgt, v0, sbl1[2 * l]),     0.f);
    float o1 = fmaxf(fmaf(wgt, v1, sbl1[2 * l + 1]), 0.f);
    float p2 = o0 * sWl2[2 * l] + o1 * sWl2[2 * l + 1];
#pragma unroll
    for (int o = 16; o > 0; o >>= 1) p2 += __shfl_xor_sync(0xffffffffu, p2, o);
    if (l == 0) out[e] = p2 + __ldg(bl2);
}

// ---------------- launch -----------------------------------------------------
extern "C" void kernel_launch(void* const* d_in, const int* in_sizes, int n_in,
                              void* d_out, int out_size) {
    const float* node_feat = (const float*)d_in[0];
    const float* edge_feat = (const float*)d_in[1];
    const int*   src       = (const int*)d_in[2];
    const int*   dst       = (const int*)d_in[3];
    const float* W1s = (const float*)d_in[4];
    const float* W1n = (const float*)d_in[5];
    const float* b1  = (const float*)d_in[6];
    const float* W2s = (const float*)d_in[7];
    const float* W2n = (const float*)d_in[8];
    const float* b2  = (const float*)d_in[9];
    const float* Wnp = (const float*)d_in[10];
    const float* bnp = (const float*)d_in[11];
    const float* We1 = (const float*)d_in[12];
    const float* be1 = (const float*)d_in[13];
    const float* We2 = (const float*)d_in[14];
    const float* be2 = (const float*)d_in[15];
    const float* Wl1 = (const float*)d_in[16];
    const float* bl1 = (const float*)d_in[17];
    const float* Wl2 = (const float*)d_in[18];
    const float* bl2 = (const float*)d_in[19];
    float* out = (float*)d_out;

    float *pp, *ph1, *ph2;
    __half2 *pst, *pdt;
    cudaGetSymbolAddress((void**)&pp,  g_p);
    cudaGetSymbolAddress((void**)&ph1, g_h1);
    cudaGetSymbolAddress((void**)&ph2, g_h2);
    cudaGetSymbolAddress((void**)&pst, g_srct);
    cudaGetSymbolAddress((void**)&pdt, g_dstt);

    int nb = (NN + 1023) / 1024;
    int nblk = (NN + 7) / 8;

    k_zero<<<512, 256>>>();
    k_deg<<<(NE + 255) / 256, 256>>>(dst);
    k_scan1<<<nb, 1024>>>();
    k_scan2<<<1, 128>>>(nb);
    k_scan3<<<(NN + 255) / 256, 256>>>();
    k_scatter<<<(NE + 255) / 256, 256>>>(src, dst);

    // Layer 1
    k_proj1<<<(NN * HD + 255) / 256, 256>>>(node_feat, W1n);
    k_sage1<<<nblk, 256>>>(node_feat, W1s, b1);

    // Layer 2: p2 = h1@W2n into g_p, then combine
    k_gemv64<<<nblk, 256>>>(ph1, W2n, nullptr, pp, 0);
    k_sage2<<<nblk, 256>>>(W2s, b2);

    // hp = relu(h2@Wnp + bnp) into g_h1 (h1 no longer needed)
    k_gemv64<<<nblk, 256>>>(ph2, Wnp, bnp, ph1, 1);

    // per-node edge-MLP tables (fp16)
    k_tab<<<nblk, 256>>>(ph1, We1,           Wl1,           pst); // src-role rows 0..63
    k_tab<<<nblk, 256>>>(ph1, We1 + 64 * HD, Wl1 + 64 * HD, pdt); // dst-role rows 64..127

    // fused edge stage
    k_edge<<<NE / 8, 256>>>(src, dst, edge_feat,
                            We1, be1, We2, be2, Wl1, bl1, Wl2, bl2, out);
}

// round 5
// speedup vs baseline: 1.3521x; 1.3149x over previous
#include <cuda_runtime.h>
#include <cuda_fp16.h>

#define NN 100000
#define NE 1600000
#define HD 64

// ---------------- scratch (device globals; no allocation allowed) ----------
__device__ int   g_deg[NN];
__device__ float g_inv[NN];
__device__ int   g_off[NN + 1];
__device__ int   g_bsum[128];
__device__ int   g_cnt[NN];
__device__ int   g_csr_src[NE];
__device__ __half2 g_p16[NN * 32];   // projected neighbor features (half2 pairs)
__device__ float g_h1[NN * HD];      // h1, later reused as hp
__device__ float g_h2[NN * HD];
__device__ uint2 g_srct[NN * 32];    // interleaved: {We-pair(half2), Wl-pair(half2)}
__device__ uint2 g_dstt[NN * 32];

__device__ __forceinline__ float tanh_fast(float x) {
    float y;
    asm("tanh.approx.f32 %0, %1;" : "=f"(y) : "f"(x));
    return y;
}

// ---------------- init ------------------------------------------------------
__global__ void k_zero() {
    int i = blockIdx.x * blockDim.x + threadIdx.x;
    int stride = gridDim.x * blockDim.x;
    for (int j = i; j < NN; j += stride) { g_deg[j] = 0; g_cnt[j] = 0; }
    if (i < 128) g_bsum[i] = 0;
}

// ---------------- degree histogram -----------------------------------------
__global__ void k_deg(const int* __restrict__ dst) {
    int e = blockIdx.x * blockDim.x + threadIdx.x;
    if (e < NE) atomicAdd(&g_deg[dst[e]], 1);
}

// ---------------- exclusive scan (3 kernels) --------------------------------
__global__ void k_scan1() {
    __shared__ int sh[1024];
    int tid = threadIdx.x;
    int i = blockIdx.x * 1024 + tid;
    int v = (i < NN) ? g_deg[i] : 0;
    sh[tid] = v;
    __syncthreads();
    for (int o = 1; o < 1024; o <<= 1) {
        int t = (tid >= o) ? sh[tid - o] : 0;
        __syncthreads();
        sh[tid] += t;
        __syncthreads();
    }
    if (i < NN) g_off[i] = sh[tid] - v;
    if (tid == 1023) g_bsum[blockIdx.x] = sh[1023];
}

__global__ void k_scan2(int nb) {
    __shared__ int sh[128];
    int tid = threadIdx.x;
    int v = (tid < nb) ? g_bsum[tid] : 0;
    sh[tid] = v;
    __syncthreads();
    for (int o = 1; o < 128; o <<= 1) {
        int t = (tid >= o) ? sh[tid - o] : 0;
        __syncthreads();
        sh[tid] += t;
        __syncthreads();
    }
    g_bsum[tid] = sh[tid] - v;
    if (tid == 127) g_off[NN] = sh[127];
}

__global__ void k_scan3() {
    int i = blockIdx.x * blockDim.x + threadIdx.x;
    if (i < NN) {
        g_off[i] += g_bsum[i >> 10];
        int d = g_deg[i];
        g_inv[i] = 1.0f / (float)(d > 0 ? d : 1);
    }
}

// ---------------- CSR scatter ------------------------------------------------
__global__ void k_scatter(const int* __restrict__ src, const int* __restrict__ dst) {
    int e = blockIdx.x * blockDim.x + threadIdx.x;
    if (e < NE) {
        int d = dst[e];
        int pos = atomicAdd(&g_cnt[d], 1);
        g_csr_src[g_off[d] + pos] = src[e];
    }
}

// ---------------- p1 = node_feat @ W1n  (4 x 64) -> half2 -------------------
__global__ void k_proj1(const float* __restrict__ nf, const float* __restrict__ W) {
    __shared__ float sW[4 * HD];
    int tid = threadIdx.x;
    sW[tid] = W[tid];                       // blockDim == 256 == 4*64
    __syncthreads();
    int idx = blockIdx.x * 256 + tid;
    if (idx >= NN * 32) return;
    int n = idx >> 5, j = idx & 31;
    const float* r = &nf[n * 4];
    float r0 = r[0], r1 = r[1], r2 = r[2], r3 = r[3];
    float v0 = r0 * sW[2*j]   + r1 * sW[64 + 2*j]   + r2 * sW[128 + 2*j]   + r3 * sW[192 + 2*j];
    float v1 = r0 * sW[2*j+1] + r1 * sW[64 + 2*j+1] + r2 * sW[128 + 2*j+1] + r3 * sW[192 + 2*j+1];
    g_p16[idx] = __floats2half2_rn(v0, v1);
}

// ---------------- SAGE layer 1 ----------------------------------------------
__global__ void k_sage1(const float* __restrict__ nf, const float* __restrict__ Ws,
                        const float* __restrict__ b) {
    __shared__ float sW[4 * HD];
    int tid = threadIdx.x;
    sW[tid] = Ws[tid];
    __syncthreads();
    int n = blockIdx.x * 8 + (tid >> 5);
    int l = tid & 31;
    if (n >= NN) return;
    int beg = g_off[n], end = g_off[n + 1];
    float ax = 0.f, ay = 0.f;
    int j = beg;
    for (; j + 4 <= end; j += 4) {
        int s0 = g_csr_src[j], s1 = g_csr_src[j + 1];
        int s2 = g_csr_src[j + 2], s3 = g_csr_src[j + 3];
        float2 q0 = __half22float2(g_p16[s0 * 32 + l]);
        float2 q1 = __half22float2(g_p16[s1 * 32 + l]);
        float2 q2 = __half22float2(g_p16[s2 * 32 + l]);
        float2 q3 = __half22float2(g_p16[s3 * 32 + l]);
        ax += (q0.x + q1.x) + (q2.x + q3.x);
        ay += (q0.y + q1.y) + (q2.y + q3.y);
    }
    for (; j < end; j++) {
        float2 q = __half22float2(g_p16[g_csr_src[j] * 32 + l]);
        ax += q.x; ay += q.y;
    }
    float iv = g_inv[n];
    const float* r = &nf[n * 4];
    float n0 = r[0], n1 = r[1], n2 = r[2], n3 = r[3];
    float sx = n0*sW[2*l]   + n1*sW[64+2*l]   + n2*sW[128+2*l]   + n3*sW[192+2*l];
    float sy = n0*sW[2*l+1] + n1*sW[64+2*l+1] + n2*sW[128+2*l+1] + n3*sW[192+2*l+1];
    float2 o;
    o.x = fmaxf(sx + ax * iv + b[2*l],     0.f);
    o.y = fmaxf(sy + ay * iv + b[2*l+1],   0.f);
    *(float2*)&g_h1[(size_t)n * HD + 2*l] = o;
}

// -------- register-blocked GEMM: 8 nodes/warp, fp32 out ---------------------
__global__ void k_gemm8f(const float* __restrict__ in, const float* __restrict__ W,
                         const float* __restrict__ bias, float* __restrict__ out,
                         int doRelu) {
    __shared__ float sW[HD * HD];
    __shared__ float sh[8][8 * HD];
    int tid = threadIdx.x, w = tid >> 5, l = tid & 31;
    for (int i = tid; i < HD * HD; i += 256) sW[i] = W[i];
    int nbase = blockIdx.x * 64 + w * 8;
    int lim = (NN - nbase) * HD;            // may be <= 0
    const float* src = in + (size_t)nbase * HD;
    for (int t = l; t < 8 * HD; t += 32) if (t < lim) sh[w][t] = src[t];
    __syncthreads();
    if (nbase >= NN) return;
    float2 acc[8];
#pragma unroll
    for (int i = 0; i < 8; i++) acc[i] = make_float2(0.f, 0.f);
#pragma unroll 8
    for (int k = 0; k < HD; k++) {
        float2 wv = *(const float2*)&sW[k * HD + 2 * l];
#pragma unroll
        for (int i = 0; i < 8; i++) {
            float hk = sh[w][i * HD + k];
            acc[i].x = fmaf(hk, wv.x, acc[i].x);
            acc[i].y = fmaf(hk, wv.y, acc[i].y);
        }
    }
    float bx = 0.f, by = 0.f;
    if (bias) { bx = bias[2 * l]; by = bias[2 * l + 1]; }
#pragma unroll
    for (int i = 0; i < 8; i++) {
        int n = nbase + i;
        if (n < NN) {
            float ox = acc[i].x + bx, oy = acc[i].y + by;
            if (doRelu) { ox = fmaxf(ox, 0.f); oy = fmaxf(oy, 0.f); }
            *(float2*)&out[(size_t)n * HD + 2 * l] = make_float2(ox, oy);
        }
    }
}

// -------- register-blocked GEMM: 8 nodes/warp, half2 out (for p2) -----------
__global__ void k_gemm8h(const float* __restrict__ in, const float* __restrict__ W) {
    __shared__ float sW[HD * HD];
    __shared__ float sh[8][8 * HD];
    int tid = threadIdx.x, w = tid >> 5, l = tid & 31;
    for (int i = tid; i < HD * HD; i += 256) sW[i] = W[i];
    int nbase = blockIdx.x * 64 + w * 8;
    int lim = (NN - nbase) * HD;
    const float* src = in + (size_t)nbase * HD;
    for (int t = l; t < 8 * HD; t += 32) if (t < lim) sh[w][t] = src[t];
    __syncthreads();
    if (nbase >= NN) return;
    float2 acc[8];
#pragma unroll
    for (int i = 0; i < 8; i++) acc[i] = make_float2(0.f, 0.f);
#pragma unroll 8
    for (int k = 0; k < HD; k++) {
        float2 wv = *(const float2*)&sW[k * HD + 2 * l];
#pragma unroll
        for (int i = 0; i < 8; i++) {
            float hk = sh[w][i * HD + k];
            acc[i].x = fmaf(hk, wv.x, acc[i].x);
            acc[i].y = fmaf(hk, wv.y, acc[i].y);
        }
    }
#pragma unroll
    for (int i = 0; i < 8; i++) {
        int n = nbase + i;
        if (n < NN) g_p16[(size_t)n * 32 + l] = __floats2half2_rn(acc[i].x, acc[i].y);
    }
}

// ---------------- SAGE layer 2 combine: h2 = relu(h2 + agg*inv + b2) --------
__global__ void k_sage2b(const float* __restrict__ b) {
    int tid = threadIdx.x;
    int n = blockIdx.x * 8 + (tid >> 5);
    int l = tid & 31;
    if (n >= NN) return;
    int beg = g_off[n], end = g_off[n + 1];
    float ax = 0.f, ay = 0.f;
    int j = beg;
    for (; j + 4 <= end; j += 4) {
        int s0 = g_csr_src[j], s1 = g_csr_src[j + 1];
        int s2 = g_csr_src[j + 2], s3 = g_csr_src[j + 3];
        float2 q0 = __half22float2(g_p16[s0 * 32 + l]);
        float2 q1 = __half22float2(g_p16[s1 * 32 + l]);
        float2 q2 = __half22float2(g_p16[s2 * 32 + l]);
        float2 q3 = __half22float2(g_p16[s3 * 32 + l]);
        ax += (q0.x + q1.x) + (q2.x + q3.x);
        ay += (q0.y + q1.y) + (q2.y + q3.y);
    }
    for (; j < end; j++) {
        float2 q = __half22float2(g_p16[g_csr_src[j] * 32 + l]);
        ax += q.x; ay += q.y;
    }
    float iv = g_inv[n];
    float2 t = *(const float2*)&g_h2[(size_t)n * HD + 2 * l];
    float2 o;
    o.x = fmaxf(t.x + ax * iv + b[2 * l],     0.f);
    o.y = fmaxf(t.y + ay * iv + b[2 * l + 1], 0.f);
    *(float2*)&g_h2[(size_t)n * HD + 2 * l] = o;
}

// -------- tables: tab[n] interleaved {hp@Wa pair, hp@Wb pair} as half2s -----
__global__ void k_tabk(const float* __restrict__ hp, const float* __restrict__ Wa,
                       const float* __restrict__ Wb, uint2* __restrict__ tab) {
    __shared__ float sWa[HD * HD];
    __shared__ float sWb[HD * HD];
    __shared__ float sh[8][8 * HD];
    int tid = threadIdx.x, w = tid >> 5, l = tid & 31;
    for (int i = tid; i < HD * HD; i += 256) { sWa[i] = Wa[i]; sWb[i] = Wb[i]; }
    int nbase = blockIdx.x * 64 + w * 8;
    int lim = (NN - nbase) * HD;
    const float* src = hp + (size_t)nbase * HD;
    for (int t = l; t < 8 * HD; t += 32) if (t < lim) sh[w][t] = src[t];
    __syncthreads();
    if (nbase >= NN) return;
    float2 aa[8], ab[8];
#pragma unroll
    for (int i = 0; i < 8; i++) { aa[i] = make_float2(0.f, 0.f); ab[i] = make_float2(0.f, 0.f); }
#pragma unroll 4
    for (int k = 0; k < HD; k++) {
        float2 wa = *(const float2*)&sWa[k * HD + 2 * l];
        float2 wb = *(const float2*)&sWb[k * HD + 2 * l];
#pragma unroll
        for (int i = 0; i < 8; i++) {
            float hk = sh[w][i * HD + k];
            aa[i].x = fmaf(hk, wa.x, aa[i].x);
            aa[i].y = fmaf(hk, wa.y, aa[i].y);
            ab[i].x = fmaf(hk, wb.x, ab[i].x);
            ab[i].y = fmaf(hk, wb.y, ab[i].y);
        }
    }
#pragma unroll
    for (int i = 0; i < 8; i++) {
        int n = nbase + i;
        if (n < NN) {
            __half2 ha = __floats2half2_rn(aa[i].x, aa[i].y);
            __half2 hb = __floats2half2_rn(ab[i].x, ab[i].y);
            uint2 v;
            v.x = *(unsigned int*)&ha;
            v.y = *(unsigned int*)&hb;
            tab[(size_t)n * 32 + l] = v;
        }
    }
}

// ---------------- edge kernel: persistent warps, register weights -----------
__global__ void k_edge(const int* __restrict__ src, const int* __restrict__ dst,
                       const float* __restrict__ ef,
                       const float* __restrict__ We1, const float* __restrict__ be1,
                       const float* __restrict__ We2, const float* __restrict__ be2,
                       const float* __restrict__ Wl1, const float* __restrict__ bl1,
                       const float* __restrict__ Wl2, const float* __restrict__ bl2,
                       float* __restrict__ out) {
    int l = threadIdx.x & 31;
    int warp = (blockIdx.x * blockDim.x + threadIdx.x) >> 5;
    int nw = (gridDim.x * blockDim.x) >> 5;

    // per-warp-lifetime constants in registers
    float2 we5[5], wl5[5];
#pragma unroll
    for (int k = 0; k < 5; k++) {
        we5[k] = *(const float2*)&We1[(128 + k) * HD + 2 * l];
        wl5[k] = *(const float2*)&Wl1[(128 + k) * HD + 2 * l];
    }
    float be1x = be1[2*l], be1y = be1[2*l+1];
    float bl1x = bl1[2*l], bl1y = bl1[2*l+1];
    float we2x = We2[2*l], we2y = We2[2*l+1];
    float wl2x = Wl2[2*l], wl2y = Wl2[2*l+1];
    float be2v = be2[0],   bl2v = bl2[0];

    for (int e = warp; e < NE; e += nw) {
        int s = __ldg(&src[e]);
        int d = __ldg(&dst[e]);
        uint2 ts = g_srct[(size_t)s * 32 + l];
        uint2 td = g_dstt[(size_t)d * 32 + l];
        float efl = (l < 5) ? __ldg(&ef[(size_t)e * 5 + l]) : 0.f;

        float2 a  = __half22float2(*(__half2*)&ts.x);
        float2 av = __half22float2(*(__half2*)&ts.y);
        float2 b  = __half22float2(*(__half2*)&td.x);
        float2 bv = __half22float2(*(__half2*)&td.y);

        float u0 = a.x + b.x + be1x;
        float u1 = a.y + b.y + be1y;
        float v0 = av.x + bv.x;
        float v1 = av.y + bv.y;
#pragma unroll
        for (int k = 0; k < 5; k++) {
            float ek = __shfl_sync(0xffffffffu, efl, k);
            u0 = fmaf(ek, we5[k].x, u0);
            u1 = fmaf(ek, we5[k].y, u1);
            v0 = fmaf(ek, wl5[k].x, v0);
            v1 = fmaf(ek, wl5[k].y, v1);
        }
        float part = tanh_fast(u0) * we2x + tanh_fast(u1) * we2y;
#pragma unroll
        for (int o = 16; o > 0; o >>= 1) part += __shfl_xor_sync(0xffffffffu, part, o);
        float wgt = 1.f / (1.f + __expf(-(part + be2v)));
        float o0 = fmaxf(fmaf(wgt, v0, bl1x), 0.f);
        float o1 = fmaxf(fmaf(wgt, v1, bl1y), 0.f);
        float p2 = o0 * wl2x + o1 * wl2y;
#pragma unroll
        for (int o = 16; o > 0; o >>= 1) p2 += __shfl_xor_sync(0xffffffffu, p2, o);
        if (l == 0) out[e] = p2 + bl2v;
    }
}

// ---------------- launch -----------------------------------------------------
extern "C" void kernel_launch(void* const* d_in, const int* in_sizes, int n_in,
                              void* d_out, int out_size) {
    const float* node_feat = (const float*)d_in[0];
    const float* edge_feat = (const float*)d_in[1];
    const int*   src       = (const int*)d_in[2];
    const int*   dst       = (const int*)d_in[3];
    const float* W1s = (const float*)d_in[4];
    const float* W1n = (const float*)d_in[5];
    const float* b1  = (const float*)d_in[6];
    const float* W2s = (const float*)d_in[7];
    const float* W2n = (const float*)d_in[8];
    const float* b2  = (const float*)d_in[9];
    const float* Wnp = (const float*)d_in[10];
    const float* bnp = (const float*)d_in[11];
    const float* We1 = (const float*)d_in[12];
    const float* be1 = (const float*)d_in[13];
    const float* We2 = (const float*)d_in[14];
    const float* be2 = (const float*)d_in[15];
    const float* Wl1 = (const float*)d_in[16];
    const float* bl1 = (const float*)d_in[17];
    const float* Wl2 = (const float*)d_in[18];
    const float* bl2 = (const float*)d_in[19];
    float* out = (float*)d_out;

    float *ph1, *ph2;
    uint2 *pst, *pdt;
    cudaGetSymbolAddress((void**)&ph1, g_h1);
    cudaGetSymbolAddress((void**)&ph2, g_h2);
    cudaGetSymbolAddress((void**)&pst, g_srct);
    cudaGetSymbolAddress((void**)&pdt, g_dstt);

    int nb   = (NN + 1023) / 1024;
    int nblk = (NN + 7) / 8;          // warp-per-node kernels
    int gblk = (NN + 63) / 64;        // 8-node-blocked GEMM kernels

    k_zero<<<512, 256>>>();
    k_deg<<<(NE + 255) / 256, 256>>>(dst);
    k_scan1<<<nb, 1024>>>();
    k_scan2<<<1, 128>>>(nb);
    k_scan3<<<(NN + 255) / 256, 256>>>();
    k_scatter<<<(NE + 255) / 256, 256>>>(src, dst);

    // Layer 1
    k_proj1<<<(NN * 32 + 255) / 256, 256>>>(node_feat, W1n);
    k_sage1<<<nblk, 256>>>(node_feat, W1s, b1);

    // Layer 2: p2 = h1@W2n (half2), t = h1@W2s (fp32), then combine
    k_gemm8h<<<gblk, 256>>>(ph1, W2n);
    k_gemm8f<<<gblk, 256>>>(ph1, W2s, nullptr, ph2, 0);
    k_sage2b<<<nblk, 256>>>(b2);

    // hp = relu(h2@Wnp + bnp) into g_h1
    k_gemm8f<<<gblk, 256>>>(ph2, Wnp, bnp, ph1, 1);

    // per-node interleaved half2 tables
    k_tabk<<<gblk, 256>>>(ph1, We1,           Wl1,           pst); // src-role rows 0..63
    k_tabk<<<gblk, 256>>>(ph1, We1 + 64 * HD, Wl1 + 64 * HD, pdt); // dst-role rows 64..127

    // persistent fused edge stage
    k_edge<<<1184, 256>>>(src, dst, edge_feat,
                          We1, be1, We2, be2, Wl1, bl1, Wl2, bl2, out);
}